// round 16
// baseline (speedup 1.0000x reference)
#include <cuda_runtime.h>
#include <math_constants.h>

// Problem constants (fixed by the dataset)
constexpr int B  = 8;
constexpr int T  = 256;
constexpr int U  = 64;
constexpr int U1 = U + 1;    // 65
constexpr int V1 = 1024;
constexpr int ROWS = B * T * U1;   // 133120 softmax rows

constexpr int SB = 66;                             // blank row stride (2-way bank conflicts)
constexpr int BLANK_N = ((T + 1) * SB + 3) & ~3;   // global blank table floats per batch

// dp smem layout: 64 pad rows (t<0, -1e30) + data + reserved top rows (never
// ancestors of harvested cells; may hold garbage).
constexpr int PADR    = 64;
constexpr int BROWS   = 385;                        // rows d-u+64 in [0,383] + b0 prefetch row 384
constexpr int LROWS   = 384;
constexpr int SBLANK_W = (BROWS * SB + 3) & ~3;     // 25412 words (keeps label float4-aligned)
constexpr int SLABEL_W = LROWS * U;                 // 24576 words
constexpr int DP_SMEM  = (SBLANK_W + SLABEL_W) * 4; // 199,952 B

constexpr float LOG2E = 1.4426950408889634f;
constexpr float LN2   = 0.6931471805599453f;
constexpr float NEG   = -1.0e30f;   // finite "minus infinity" (absorbing in fp32)

// Scratch (device globals — no allocation allowed)
// g blank layout per batch: T+1 rows of stride SB; row 0 = -1e30 pad (t=-1),
// row k holds lp2_blank[t=k-1][:]  (lp2 = log-prob * log2(e))
__device__ float g_lp2_blankP[B * BLANK_N];
__device__ float g_lp2_label [B * T * U];
__device__ float g_sum;      // zero-init
__device__ int   g_ctr;      // zero-init

__device__ __forceinline__ float ex2f(float x) {
    float r; asm("ex2.approx.ftz.f32 %0, %1;" : "=f"(r) : "f"(x)); return r;
}
__device__ __forceinline__ float lg2f(float x) {
    float r; asm("lg2.approx.ftz.f32 %0, %1;" : "=f"(r) : "f"(x)); return r;
}

// ---------------------------------------------------------------------------
// Kernel 1: per-row logsumexp + gather blank/label log-probs (log2 domain).
// One warp per row of 1024 floats. HBM-roofline bound (86% DRAM). Unchanged.
// ---------------------------------------------------------------------------
__global__ __launch_bounds__(256) void lse_gather_kernel(
    const float* __restrict__ logits, const int* __restrict__ y)
{
    int warp = (blockIdx.x * blockDim.x + threadIdx.x) >> 5;
    int lane = threadIdx.x & 31;
    if (warp >= ROWS) return;

    const float4* row = reinterpret_cast<const float4*>(logits) + (size_t)warp * (V1 / 4);

    float4 v[8];
#pragma unroll
    for (int j = 0; j < 8; j++) v[j] = row[lane + j * 32];

    float m = -CUDART_INF_F;
#pragma unroll
    for (int j = 0; j < 8; j++)
        m = fmaxf(m, fmaxf(fmaxf(v[j].x, v[j].y), fmaxf(v[j].z, v[j].w)));
#pragma unroll
    for (int o = 16; o > 0; o >>= 1) m = fmaxf(m, __shfl_xor_sync(0xFFFFFFFFu, m, o));

    float s = 0.f;
#pragma unroll
    for (int j = 0; j < 8; j++)
        s += __expf(v[j].x - m) + __expf(v[j].y - m) +
             __expf(v[j].z - m) + __expf(v[j].w - m);
#pragma unroll
    for (int o = 16; o > 0; o >>= 1) s += __shfl_xor_sync(0xFFFFFFFFu, s, o);

    float lse = m + __logf(s);

    int b   = warp / (T * U1);
    int rem = warp % (T * U1);
    int t   = rem / U1;
    int u   = rem % U1;

    float* bp = g_lp2_blankP + (size_t)b * BLANK_N;

    if (lane == 0) {
        bp[(t + 1) * SB + u] = (v[0].x - lse) * LOG2E;   // lane 0 holds element 0
    }
    if (t == 0 && lane == 2) {
        bp[u] = NEG;                                     // pad row (t = -1)
    }
    if (u < U && lane == 1) {
        int lab = y[b * U + u];                          // never 0 (blank)
        float lv = logits[(size_t)warp * V1 + lab];      // L1/L2 hit (just streamed)
        g_lp2_label[(size_t)(b * T + t) * U + u] = (lv - lse) * LOG2E;
    }
}

// ---------------------------------------------------------------------------
// Kernel 2: forward DP — branchless register wavefront, pointer-incremental.
// smem row r of blank holds lp2_blank[r-65]; row r of label holds
// lp2_label[r-64]; rows 0..63 are -1e30 pads (t<0), rows above the data are
// reserved-but-unwritten (cells with t>T-1 are never ancestors of the
// harvested cell (t_end<=T-1, u_end), so garbage there is unreachable).
// Per diagonal the five LDS addresses advance by constant strides — no
// clamps, no per-iteration index math. One shfl carries the cross-lane dep.
// ---------------------------------------------------------------------------
__global__ __launch_bounds__(256) void dp_kernel(
    const int* __restrict__ logit_lens, const int* __restrict__ y_lens,
    float* __restrict__ out)
{
    extern __shared__ float sm[];
    float* s_blank = sm;                 // SBLANK_W words
    float* s_label = sm + SBLANK_W;      // SLABEL_W words

    const int b   = blockIdx.x;
    const int tid = threadIdx.x;

    // ---- stage: pad rows + data (all float4, offsets 16B-aligned) ----
    {
        const float4 neg4 = make_float4(NEG, NEG, NEG, NEG);
        float4* sb4 = reinterpret_cast<float4*>(s_blank);
        float4* sl4 = reinterpret_cast<float4*>(s_label);
        for (int i = tid; i < (PADR * SB) / 4; i += 256) sb4[i] = neg4;   // 1056
        for (int i = tid; i < (PADR * U)  / 4; i += 256) sl4[i] = neg4;   // 1024

        const float4* gb4 = reinterpret_cast<const float4*>(g_lp2_blankP + (size_t)b * BLANK_N);
        const float4* gl4 = reinterpret_cast<const float4*>(g_lp2_label  + (size_t)b * T * U);
        // g blank row k lands at smem row 64+k  (row 64 = g pad row 0 = t-1 < 0)
        for (int i = tid; i < BLANK_N / 4; i += 256) sb4[i + (PADR * SB) / 4] = gb4[i];
        // g label row t lands at smem row 64+t
        for (int i = tid; i < (T * U) / 4; i += 256) sl4[i + (PADR * U) / 4] = gl4[i];
    }
    __syncthreads();
    if (tid >= 32) return;

    const int lane = tid;
    const int u_lo = 2 * lane + 1;   // 1..63
    const int u_hi = 2 * lane + 2;   // 2..64

    const int t_end = logit_lens[b] - 1;
    const int u_end = y_lens[b];
    const int d_tgt = t_end + u_end;          // in [1, 319]; loop ends exactly here

    float a0   = (lane == 0) ? 0.f : NEG;
    float a_lo = NEG;
    float a_hi = NEG;

    // Incremental pointers for d = 1:
    //   blank row for cell (t=d-u, u) is r = d-u+64  (holds lp2_blank[t-1])
    //   label row is r = d-u+64                      (holds lp2_label[t])
    const float* pb  = s_blank + (65 - u_lo) * SB + u_lo;        // bl_lo; bl_hi = pb[1-SB]
    const float* pl  = s_label + (65 - u_lo) * U  + (u_lo - 1);  // lb_lo; lb_hi = pl[1-U]
    const float* pb0 = s_blank + 65 * SB;                        // blank[d-1][0]

    // prefetch diagonal 1
    float bl_lo = pb[0], bl_hi = pb[1 - SB];
    float lb_lo = pl[0], lb_hi = pl[1 - U];
    float b0    = pb0[0];
    pb += SB; pl += U; pb0 += SB;

#pragma unroll 4
    for (int d = 1; d <= d_tgt; d++) {
        // consume current diagonal's prefetched values
        const float cbl_lo = bl_lo, cbl_hi = bl_hi;
        const float clb_lo = lb_lo, clb_hi = lb_hi;
        const float cb0    = b0;

        // prefetch diagonal d+1 (pointer-incremental; always in-bounds:
        // max row at d+1 = d_tgt+1 <= 320 -> r <= 383 (<BROWS), b0 row <= 384)
        bl_lo = pb[0]; bl_hi = pb[1 - SB];
        lb_lo = pl[0]; lb_hi = pl[1 - U];
        b0    = pb0[0];
        pb += SB; pl += U; pb0 += SB;

        // previous-diagonal alpha values
        float p0   = a0;
        float p_lo = a_lo;
        float p_hi = a_hi;
        float fl   = __shfl_up_sync(0xFFFFFFFFu, a_hi, 1);   // prev[u_lo-1]
        fl = (lane == 0) ? p0 : fl;

        // u = 0 chain (meaningful on lane 0 only; harmless elsewhere)
        a0 = p0 + cb0;

        // u_lo cell
        float aL = p_lo + cbl_lo;
        float cL = fl   + clb_lo;
        float mL = fmaxf(aL, cL);
        a_lo = mL + lg2f(1.f + ex2f(-fabsf(aL - cL)));

        // u_hi cell (prev[u_hi-1] = p_lo, own register)
        float aH = p_hi + cbl_hi;
        float cH = p_lo + clb_hi;
        float mH = fmaxf(aH, cH);
        a_hi = mH + lg2f(1.f + ex2f(-fabsf(aH - cH)));
    }

    // Harvest: loop exited with state at diagonal d_tgt.
    float res = NEG;
    res = (u_end == u_lo)           ? a_lo : res;
    res = (u_end == u_hi)           ? a_hi : res;
    res = (lane == 0 && u_end == 0) ? a0   : res;

    // reduce the single matched value across the warp
    float cand = fmaxf(res, -3.0e38f);
#pragma unroll
    for (int o = 16; o > 0; o >>= 1)
        cand = fmaxf(cand, __shfl_xor_sync(0xFFFFFFFFu, cand, o));

    if (lane == 0) {
        float bfin = s_blank[(t_end + 65) * SB + u_end];     // lp2_blank[t_end][u_end]
        float ll   = (cand + bfin) * LN2;                    // back to natural log

        atomicAdd(&g_sum, ll);
        __threadfence();
        int old = atomicAdd(&g_ctr, 1);
        if (old == B - 1) {
            __threadfence();
            float total = atomicAdd(&g_sum, 0.f);            // atomic read of final sum
            out[0] = -total / (float)B;
            g_sum = 0.f;                                     // reset for next replay
            g_ctr = 0;
        }
    }
}

extern "C" void kernel_launch(void* const* d_in, const int* in_sizes, int n_in,
                              void* d_out, int out_size)
{
    const float* logits     = (const float*)d_in[0];   // [B,T,U+1,V1] fp32
    const int*   logit_lens = (const int*)d_in[1];     // [B]
    const int*   y          = (const int*)d_in[2];     // [B,U]
    const int*   y_lens     = (const int*)d_in[3];     // [B]
    float*       out        = (float*)d_out;

    // Phase 1: 133120 rows, 8 warps per 256-thread block (HBM-roofline bound)
    int blocks = (ROWS + 7) / 8;   // 16640
    lse_gather_kernel<<<blocks, 256>>>(logits, y);

    // Phase 2: pointer-incremental branchless DP + fused final reduction
    cudaFuncSetAttribute(dp_kernel, cudaFuncAttributeMaxDynamicSharedMemorySize, DP_SMEM);
    dp_kernel<<<B, 256, DP_SMEM>>>(logit_lens, y_lens, out);
}